// round 11
// baseline (speedup 1.0000x reference)
#include <cuda_runtime.h>
#include <math.h>

#define NEGV (-1e9f)
typedef unsigned long long ull;

__device__ float g_pool1[16*98*148*32];
__device__ float g_pool2[16*12*18*64];
__device__ float g_x3[16*1536];
__device__ float g_part[2*16*48000];
__device__ float4 g_cand_box[76800];
__device__ float4 g_cand_meta[76800];   // (score, area, unused, cls)
__device__ ull    g_round_key[20];
__device__ int    g_bar_count;
__device__ volatile int g_bar_phase;

__device__ __forceinline__ float sigmoidf_(float x) { return 1.f / (1.f + expf(-x)); }

__device__ __forceinline__ void fma2(ull& d, ull a, ull b) {
    asm("fma.rn.f32x2 %0, %1, %2, %0;" : "+l"(d) : "l"(a), "l"(b));
}
__device__ __forceinline__ ull pack2(float lo, float hi) {
    ull r; asm("mov.b64 %0, {%1, %2};" : "=l"(r) : "f"(lo), "f"(hi)); return r;
}
__device__ __forceinline__ float2 unpack2(ull v) {
    float2 f; asm("mov.b64 {%0, %1}, %2;" : "=f"(f.x), "=f"(f.y) : "l"(v)); return f;
}

// conv1 (10x10 s2) + relu + maxpool2 fused. grid(10,98,16), 256 thr.  [unchanged]
__global__ __launch_bounds__(256) void conv1_pool_kernel(
    const float* __restrict__ img, const float* __restrict__ w1,
    const float* __restrict__ b1)
{
    __shared__ float s_w[9600];
    __shared__ float s_in[3*12*72];
    const int b = blockIdx.z, py = blockIdx.y, px0 = blockIdx.x * 16;
    const int tid = threadIdx.x, lane = tid & 31, wid = tid >> 5;

    for (int i = tid; i < 9600; i += 256) s_w[i] = w1[i];
    const int y0 = py * 4, x0 = px0 * 4;
    for (int i = tid; i < 3*12*72; i += 256) {
        int ci = i / (12*72), rj = i - ci*(12*72);
        int r = rj / 72, j = rj - r*72, x = x0 + j;
        s_in[i] = (x < 600) ? img[((b*400 + y0 + r)*600 + x)*3 + ci] : 0.f;
    }
    __syncthreads();

    float acc[2][4];
#pragma unroll
    for (int p = 0; p < 2; ++p) { acc[p][0]=acc[p][1]=acc[p][2]=acc[p][3]=0.f; }
    const int xb = wid * 8;

#pragma unroll
    for (int ky = 0; ky < 10; ++ky) {
#pragma unroll
        for (int ci = 0; ci < 3; ++ci) {
            float xr[2][16];
#pragma unroll
            for (int dy = 0; dy < 2; ++dy) {
                const float* rp = &s_in[ci*(12*72) + (ky + 2*dy)*72 + xb];
#pragma unroll
                for (int v = 0; v < 4; ++v) {
                    float4 tv = *(const float4*)(rp + v*4);
                    xr[dy][v*4+0]=tv.x; xr[dy][v*4+1]=tv.y; xr[dy][v*4+2]=tv.z; xr[dy][v*4+3]=tv.w;
                }
            }
#pragma unroll
            for (int kx = 0; kx < 10; ++kx) {
                float wv = s_w[((ky*10 + kx)*3 + ci)*32 + lane];
#pragma unroll
                for (int p = 0; p < 2; ++p)
#pragma unroll
                    for (int dy = 0; dy < 2; ++dy)
#pragma unroll
                        for (int dx = 0; dx < 2; ++dx)
                            acc[p][dy*2+dx] = fmaf(xr[dy][4*p + 2*dx + kx], wv, acc[p][dy*2+dx]);
            }
        }
    }
    float bias = b1[lane];
#pragma unroll
    for (int p = 0; p < 2; ++p) {
        int px = px0 + wid*2 + p;
        if (px < 148) {
            float m = fmaxf(fmaxf(acc[p][0], acc[p][1]), fmaxf(acc[p][2], acc[p][3]));
            g_pool1[((b*98 + py)*148 + px)*32 + lane] = fmaxf(m + bias, 0.f);
        }
    }
}

// conv2 (4x4 s4) + relu + maxpool2. grid(9,6,16), 256 thr  [unchanged]
__global__ __launch_bounds__(256) void conv2_pool_kernel(
    const float* __restrict__ w2, const float* __restrict__ b2)
{
    __shared__ float s_in[16*16*32];
    const int b = blockIdx.z;
    const int py0 = blockIdx.y * 2, px0 = blockIdx.x * 2;
    const int tid = threadIdx.x;
    const int c = tid & 63, sp = tid >> 6;
    const int spy = sp >> 1, spx = sp & 1;
    const int y0 = py0*8, x0 = px0*8;
    for (int i = tid; i < 8192; i += 256) {
        int ci = i & 31, cx = (i >> 5) & 15, r = i >> 9;
        s_in[i] = g_pool1[((b*98 + y0 + r)*148 + x0 + cx)*32 + ci];
    }
    __syncthreads();
    const int rb = spy*8, cb = spx*8;
    float acc[4] = {0.f,0.f,0.f,0.f};
#pragma unroll
    for (int ky = 0; ky < 4; ++ky)
#pragma unroll
        for (int kx = 0; kx < 4; ++kx)
#pragma unroll 8
            for (int ci = 0; ci < 32; ++ci) {
                float wv = __ldg(&w2[((ky*4 + kx)*32 + ci)*64 + c]);
#pragma unroll
                for (int dy = 0; dy < 2; ++dy)
#pragma unroll
                    for (int dx = 0; dx < 2; ++dx)
                        acc[dy*2+dx] = fmaf(s_in[((rb + 4*dy + ky)*16 + cb + 4*dx + kx)*32 + ci], wv, acc[dy*2+dx]);
            }
    float m = fmaxf(fmaxf(acc[0], acc[1]), fmaxf(acc[2], acc[3]));
    g_pool2[((b*12 + py0 + spy)*18 + px0 + spx)*64 + c] = fmaxf(m + b2[c], 0.f);
}

// conv3 (4x4 s4) + relu. grid(4,3,16), 128 thr  [unchanged]
__global__ __launch_bounds__(128) void conv3_kernel(
    const float* __restrict__ w3, const float* __restrict__ b3)
{
    __shared__ float s_in[1024];
    const int b = blockIdx.z, oy = blockIdx.y, ox = blockIdx.x;
    const int tid = threadIdx.x;
    for (int i = tid; i < 1024; i += 128) {
        int ci = i & 63, cx = (i >> 6) & 3, r = i >> 8;
        s_in[i] = g_pool2[((b*12 + oy*4 + r)*18 + ox*4 + cx)*64 + ci];
    }
    __syncthreads();
    float a0 = 0.f, a1 = 0.f;
    for (int i = 0; i < 1024; i += 2) {
        a0 = fmaf(s_in[i],   __ldg(&w3[i*128 + tid]),     a0);
        a1 = fmaf(s_in[i+1], __ldg(&w3[(i+1)*128 + tid]), a1);
    }
    g_x3[b*1536 + (oy*4 + ox)*128 + tid] = fmaxf(a0 + a1 + b3[tid], 0.f);
}

// dense split-K x2, f32x2, pipelined wd loads. grid(188,2), 256 thr.  [unchanged]
__global__ __launch_bounds__(256) void dense_kernel(const float* __restrict__ wd)
{
    __shared__ float2 s_x2[8*768];
    const int tid = threadIdx.x;
    const int kh = blockIdx.y, k0 = kh * 768;
    const int n = blockIdx.x * 256 + tid;
    for (int i = tid; i < 8*768; i += 256) {
        int bp = i / 768, k = i - bp*768;
        s_x2[i] = make_float2(g_x3[(2*bp)*1536 + k0 + k], g_x3[(2*bp+1)*1536 + k0 + k]);
    }
    __syncthreads();
    if (n >= 48000) return;

    ull acc[8];
#pragma unroll
    for (int bp = 0; bp < 8; ++bp) acc[bp] = 0ull;

    const float* wp = wd + (size_t)k0 * 48000 + n;
    float wA[8], wB[8];
#pragma unroll
    for (int j = 0; j < 8; ++j) wA[j] = wp[(size_t)j * 48000];

    for (int kk = 0; kk < 768; kk += 16) {
#pragma unroll
        for (int j = 0; j < 8; ++j) wB[j] = wp[(size_t)(kk + 8 + j) * 48000];
        {
            ull wq[8];
#pragma unroll
            for (int j = 0; j < 8; ++j) wq[j] = pack2(wA[j], wA[j]);
#pragma unroll
            for (int bp = 0; bp < 8; ++bp) {
                const ulonglong2* xp = (const ulonglong2*)&s_x2[bp*768 + kk];
                ulonglong2 xa = xp[0], xb = xp[1], xc = xp[2], xd = xp[3];
                fma2(acc[bp], xa.x, wq[0]); fma2(acc[bp], xa.y, wq[1]);
                fma2(acc[bp], xb.x, wq[2]); fma2(acc[bp], xb.y, wq[3]);
                fma2(acc[bp], xc.x, wq[4]); fma2(acc[bp], xc.y, wq[5]);
                fma2(acc[bp], xd.x, wq[6]); fma2(acc[bp], xd.y, wq[7]);
            }
        }
        const int kn = (kk + 16 < 768) ? (kk + 16) : 0;
#pragma unroll
        for (int j = 0; j < 8; ++j) wA[j] = wp[(size_t)(kn + j) * 48000];
        {
            ull wq[8];
#pragma unroll
            for (int j = 0; j < 8; ++j) wq[j] = pack2(wB[j], wB[j]);
#pragma unroll
            for (int bp = 0; bp < 8; ++bp) {
                const ulonglong2* xp = (const ulonglong2*)&s_x2[bp*768 + kk + 8];
                ulonglong2 xa = xp[0], xb = xp[1], xc = xp[2], xd = xp[3];
                fma2(acc[bp], xa.x, wq[0]); fma2(acc[bp], xa.y, wq[1]);
                fma2(acc[bp], xb.x, wq[2]); fma2(acc[bp], xb.y, wq[3]);
                fma2(acc[bp], xc.x, wq[4]); fma2(acc[bp], xc.y, wq[5]);
                fma2(acc[bp], xd.x, wq[6]); fma2(acc[bp], xd.y, wq[7]);
            }
        }
    }
#pragma unroll
    for (int bp = 0; bp < 8; ++bp) {
        float2 v = unpack2(acc[bp]);
        g_part[(kh*16 + 2*bp)*48000 + n]     = v.x;
        g_part[(kh*16 + 2*bp + 1)*48000 + n] = v.y;
    }
}

// epilogue: out = relu(part0 + part1 + bd); also resets NMS/barrier state
__global__ __launch_bounds__(256) void dense_epilogue_kernel(
    const float* __restrict__ bd, float* __restrict__ out)
{
    int i = blockIdx.x * 256 + threadIdx.x;
    if (i < 20) g_round_key[i] = 0ull;
    if (i == 20) { g_bar_count = 0; g_bar_phase = 0; }
    if (i >= 768000) return;
    int n = i % 48000;
    int b = i / 48000;
    float v = g_part[b*48000 + n] + g_part[(16 + b)*48000 + n] + bd[n];
    out[i] = fmaxf(v, 0.f);
}

// decode (faithful flat reshapes) + threshold; writes ALL 76800 slots at pos=j
__global__ __launch_bounds__(256) void transform_kernel(const float* __restrict__ p)
{
    const int j = blockIdx.x * 256 + threadIdx.x;

    float center[2], wh[2];
#pragma unroll
    for (int c = 0; c < 2; ++c) {
        int f = 2*j + c;
        int sa = f / 76800;  int r  = f - sa*76800;
        int sb = r / 4800;   int r2 = r - sb*4800;
        int sgy = r2 / 120;  int r3 = r2 - sgy*120;
        int sgx = r3 >> 1;   int sc = r3 & 1;
        const float* pc = p + ((sb*40 + sgy)*60 + sgx)*20;
        int off = sa ? 10 : 0;
        center[c] = sigmoidf_(pc[off + sc]) + (sc == 0 ? (float)sgx : (float)sgy);
        float anch = (sgx >= 30) ? (sc == 0 ? 0.5f : 1.0f) : (sc == 0 ? 1.0f : 0.5f);
        wh[c] = expf(pc[off + 2 + sc]) * anch;
    }
    int sa = j / 38400;  int r = j - sa*38400;
    int sb = r / 2400;   int rr = r - sb*2400;
    int sgy = rr / 60;   int sgx = rr - sgy*60;
    float obj = sigmoidf_(p[((sb*40 + sgy)*60 + sgx)*20 + (sa ? 14 : 4)]);

    float best = -1.f; int bcls = 0;
#pragma unroll
    for (int c5 = 0; c5 < 5; ++c5) {
        int g = 5*j + c5;
        int ta = g / 192000;  int q  = g - ta*192000;
        int tb = q / 12000;   int q2 = q - tb*12000;
        int tgy = q2 / 300;   int q3 = q2 - tgy*300;
        int tgx = q3 / 5;     int tc = q3 - tgx*5;
        float cl = sigmoidf_(p[((tb*40 + tgy)*60 + tgx)*20 + (ta ? 15 : 5) + tc]);
        float s = obj * cl;
        if (s > best) { best = s; bcls = c5; }
    }

    float y1 = (center[1] - wh[1]*0.5f) * 400.f;
    float x1 = (center[0] - wh[0]*0.5f) * 600.f;
    float y2 = (center[1] + wh[1]*0.5f) * 400.f;
    float x2 = (center[0] + wh[0]*0.5f) * 600.f;
    float area = fmaxf(y2 - y1, 0.f) * fmaxf(x2 - x1, 0.f);
    float score = (best >= 0.3f) ? best : NEGV;
    g_cand_box[j]  = make_float4(y1, x1, y2, x2);
    g_cand_meta[j] = make_float4(score, area, 0.f, (float)bcls);
}

// Persistent NMS: 148 blocks x 512 thr (all resident), candidates in smem,
// 20 rounds with one grid barrier each (per-round key slots -> no reset race).
#define NMS_BLOCKS 148
#define CPB 519            // candidates per block (148*519 = 76812 >= 76800)
__global__ __launch_bounds__(512) void nms_persistent_kernel(float* __restrict__ out)
{
    __shared__ float  s_score[CPB];
    __shared__ float4 s_box[CPB];
    __shared__ float  s_area[CPB];
    __shared__ ull    s_key[16];
    __shared__ float4 s_selb;
    __shared__ float  s_sela;
    __shared__ int    s_selpos;

    const int tid = threadIdx.x;
    const int base = blockIdx.x * CPB;
    const int cnt = min(CPB, 76800 - base);

    for (int i = tid; i < cnt; i += 512) {
        float4 mt = g_cand_meta[base + i];
        s_score[i] = mt.x;
        s_area[i]  = mt.y;
        s_box[i]   = g_cand_box[base + i];
    }
    __syncthreads();

    for (int t = 0; t < 20; ++t) {
        // block-local argmax among alive
        ull key = 0ull;
        for (int i = tid; i < cnt; i += 512) {
            float s = s_score[i];
            if (s != NEGV) {
                ull k = ((ull)__float_as_uint(s) << 32) | (ull)(0xffffffffu - (unsigned)(base + i));
                if (k > key) key = k;
            }
        }
#pragma unroll
        for (int off = 16; off > 0; off >>= 1) {
            ull o = __shfl_down_sync(0xffffffffu, key, off);
            if (o > key) key = o;
        }
        if ((tid & 31) == 0) s_key[tid >> 5] = key;
        __syncthreads();
        if (tid == 0) {
            ull bk = s_key[0];
#pragma unroll
            for (int w = 1; w < 16; ++w) if (s_key[w] > bk) bk = s_key[w];
            if (bk) atomicMax(&g_round_key[t], bk);
            // grid barrier (arrive)
            __threadfence();
            int ticket = atomicAdd(&g_bar_count, 1);
            if (ticket == NMS_BLOCKS - 1) {
                g_bar_count = 0;
                __threadfence();
                g_bar_phase = t + 1;
            } else {
                while (g_bar_phase < t + 1) __nanosleep(64);
            }
            // read winner
            ull k = g_round_key[t];
            if (k != 0ull) {
                int pos = (int)(0xffffffffu - (unsigned)(k & 0xffffffffu));
                float score = __uint_as_float((unsigned)(k >> 32));
                float4 bx = g_cand_box[pos];
                float4 m2 = g_cand_meta[pos];
                s_selpos = pos; s_selb = bx; s_sela = m2.y;
                if (blockIdx.x == 0) {
                    out[768080 + t] = score;
                    out[768000 + 4*t + 0] = bx.x;
                    out[768000 + 4*t + 1] = bx.y;
                    out[768000 + 4*t + 2] = bx.z;
                    out[768000 + 4*t + 3] = bx.w;
                    out[768100 + t] = m2.w;
                }
            } else {
                s_selpos = -1;
                if (blockIdx.x == 0) {
                    out[768080 + t] = 0.f;
                    out[768000 + 4*t + 0] = 0.f;
                    out[768000 + 4*t + 1] = 0.f;
                    out[768000 + 4*t + 2] = 0.f;
                    out[768000 + 4*t + 3] = 0.f;
                    out[768100 + t] = 0.f;
                }
            }
        }
        __syncthreads();
        const int selPos = s_selpos;
        if (selPos >= 0) {
            const float4 sb = s_selb;
            const float sa = s_sela;
            for (int i = tid; i < cnt; i += 512) {
                float s = s_score[i];
                if (s != NEGV) {
                    float4 bx = s_box[i];
                    float yy1 = fmaxf(sb.x, bx.x), xx1 = fmaxf(sb.y, bx.y);
                    float yy2 = fminf(sb.z, bx.z), xx2 = fminf(sb.w, bx.w);
                    float inter = fmaxf(yy2 - yy1, 0.f) * fmaxf(xx2 - xx1, 0.f);
                    float iou = inter / (sa + s_area[i] - inter + 1e-9f);
                    if (iou > 0.4f || (base + i) == selPos) s_score[i] = NEGV;
                }
            }
        }
        __syncthreads();
    }
}

extern "C" void kernel_launch(void* const* d_in, const int* in_sizes, int n_in,
                              void* d_out, int out_size) {
    const float* img = (const float*)d_in[0];
    const float* w1  = (const float*)d_in[1];
    const float* b1  = (const float*)d_in[2];
    const float* w2  = (const float*)d_in[3];
    const float* b2  = (const float*)d_in[4];
    const float* w3  = (const float*)d_in[5];
    const float* b3  = (const float*)d_in[6];
    const float* wd  = (const float*)d_in[7];
    const float* bd  = (const float*)d_in[8];
    float* out = (float*)d_out;

    conv1_pool_kernel<<<dim3(10, 98, 16), 256>>>(img, w1, b1);
    conv2_pool_kernel<<<dim3(9, 6, 16), 256>>>(w2, b2);
    conv3_kernel<<<dim3(4, 3, 16), 128>>>(w3, b3);
    dense_kernel<<<dim3(188, 2), 256>>>(wd);
    dense_epilogue_kernel<<<3000, 256>>>(bd, out);
    transform_kernel<<<300, 256>>>(out);
    nms_persistent_kernel<<<NMS_BLOCKS, 512>>>(out);
}

// round 14
// speedup vs baseline: 1.5371x; 1.5371x over previous
#include <cuda_runtime.h>
#include <stdint.h>
#include <math.h>

#define NEGV (-1e9f)
typedef unsigned long long ull;

__device__ float g_pool1[16*98*148*32];
__device__ float g_pool2[16*12*18*64];
__device__ float g_x3[16*1536];
__device__ float g_part[2*16*48000];
__device__ float4 g_cand_box[76800];
__device__ float4 g_cand_meta[76800];   // (score, area, unused, cls)
__device__ ull    g_round_key[20];
__device__ int    g_bar_count;
__device__ volatile int g_bar_phase;

__device__ __forceinline__ float sigmoidf_(float x) { return 1.f / (1.f + expf(-x)); }

__device__ __forceinline__ void fma2(ull& d, ull a, ull b) {
    asm("fma.rn.f32x2 %0, %1, %2, %0;" : "+l"(d) : "l"(a), "l"(b));
}
__device__ __forceinline__ ull pack2(float lo, float hi) {
    ull r; asm("mov.b64 %0, {%1, %2};" : "=l"(r) : "f"(lo), "f"(hi)); return r;
}
__device__ __forceinline__ float2 unpack2(ull v) {
    float2 f; asm("mov.b64 {%0, %1}, %2;" : "=f"(f.x), "=f"(f.y) : "l"(v)); return f;
}

// conv1 (10x10 s2) + relu + maxpool2 fused. grid(10,98,16), 256 thr.  [proven 546us]
__global__ __launch_bounds__(256) void conv1_pool_kernel(
    const float* __restrict__ img, const float* __restrict__ w1,
    const float* __restrict__ b1)
{
    __shared__ float s_w[9600];
    __shared__ float s_in[3*12*72];
    const int b = blockIdx.z, py = blockIdx.y, px0 = blockIdx.x * 16;
    const int tid = threadIdx.x, lane = tid & 31, wid = tid >> 5;

    for (int i = tid; i < 9600; i += 256) s_w[i] = w1[i];
    const int y0 = py * 4, x0 = px0 * 4;
    for (int i = tid; i < 3*12*72; i += 256) {
        int ci = i / (12*72), rj = i - ci*(12*72);
        int r = rj / 72, j = rj - r*72, x = x0 + j;
        s_in[i] = (x < 600) ? img[((b*400 + y0 + r)*600 + x)*3 + ci] : 0.f;
    }
    __syncthreads();

    float acc[2][4];
#pragma unroll
    for (int p = 0; p < 2; ++p) { acc[p][0]=acc[p][1]=acc[p][2]=acc[p][3]=0.f; }
    const int xb = wid * 8;

#pragma unroll
    for (int ky = 0; ky < 10; ++ky) {
#pragma unroll
        for (int ci = 0; ci < 3; ++ci) {
            float xr[2][16];
#pragma unroll
            for (int dy = 0; dy < 2; ++dy) {
                const float* rp = &s_in[ci*(12*72) + (ky + 2*dy)*72 + xb];
#pragma unroll
                for (int v = 0; v < 4; ++v) {
                    float4 tv = *(const float4*)(rp + v*4);
                    xr[dy][v*4+0]=tv.x; xr[dy][v*4+1]=tv.y; xr[dy][v*4+2]=tv.z; xr[dy][v*4+3]=tv.w;
                }
            }
#pragma unroll
            for (int kx = 0; kx < 10; ++kx) {
                float wv = s_w[((ky*10 + kx)*3 + ci)*32 + lane];
#pragma unroll
                for (int p = 0; p < 2; ++p)
#pragma unroll
                    for (int dy = 0; dy < 2; ++dy)
#pragma unroll
                        for (int dx = 0; dx < 2; ++dx)
                            acc[p][dy*2+dx] = fmaf(xr[dy][4*p + 2*dx + kx], wv, acc[p][dy*2+dx]);
            }
        }
    }
    float bias = b1[lane];
#pragma unroll
    for (int p = 0; p < 2; ++p) {
        int px = px0 + wid*2 + p;
        if (px < 148) {
            float m = fmaxf(fmaxf(acc[p][0], acc[p][1]), fmaxf(acc[p][2], acc[p][3]));
            g_pool1[((b*98 + py)*148 + px)*32 + lane] = fmaxf(m + bias, 0.f);
        }
    }
}

// conv2 (4x4 s4) + relu + maxpool2. grid(9,6,16), 256 thr  [proven]
__global__ __launch_bounds__(256) void conv2_pool_kernel(
    const float* __restrict__ w2, const float* __restrict__ b2)
{
    __shared__ float s_in[16*16*32];
    const int b = blockIdx.z;
    const int py0 = blockIdx.y * 2, px0 = blockIdx.x * 2;
    const int tid = threadIdx.x;
    const int c = tid & 63, sp = tid >> 6;
    const int spy = sp >> 1, spx = sp & 1;
    const int y0 = py0*8, x0 = px0*8;
    for (int i = tid; i < 8192; i += 256) {
        int ci = i & 31, cx = (i >> 5) & 15, r = i >> 9;
        s_in[i] = g_pool1[((b*98 + y0 + r)*148 + x0 + cx)*32 + ci];
    }
    __syncthreads();
    const int rb = spy*8, cb = spx*8;
    float acc[4] = {0.f,0.f,0.f,0.f};
#pragma unroll
    for (int ky = 0; ky < 4; ++ky)
#pragma unroll
        for (int kx = 0; kx < 4; ++kx)
#pragma unroll 8
            for (int ci = 0; ci < 32; ++ci) {
                float wv = __ldg(&w2[((ky*4 + kx)*32 + ci)*64 + c]);
#pragma unroll
                for (int dy = 0; dy < 2; ++dy)
#pragma unroll
                    for (int dx = 0; dx < 2; ++dx)
                        acc[dy*2+dx] = fmaf(s_in[((rb + 4*dy + ky)*16 + cb + 4*dx + kx)*32 + ci], wv, acc[dy*2+dx]);
            }
    float m = fmaxf(fmaxf(acc[0], acc[1]), fmaxf(acc[2], acc[3]));
    g_pool2[((b*12 + py0 + spy)*18 + px0 + spx)*64 + c] = fmaxf(m + b2[c], 0.f);
}

// conv3 (4x4 s4) + relu. grid(4,3,16), 128 thr  [proven]
__global__ __launch_bounds__(128) void conv3_kernel(
    const float* __restrict__ w3, const float* __restrict__ b3)
{
    __shared__ float s_in[1024];
    const int b = blockIdx.z, oy = blockIdx.y, ox = blockIdx.x;
    const int tid = threadIdx.x;
    for (int i = tid; i < 1024; i += 128) {
        int ci = i & 63, cx = (i >> 6) & 3, r = i >> 8;
        s_in[i] = g_pool2[((b*12 + oy*4 + r)*18 + ox*4 + cx)*64 + ci];
    }
    __syncthreads();
    float a0 = 0.f, a1 = 0.f;
    for (int i = 0; i < 1024; i += 2) {
        a0 = fmaf(s_in[i],   __ldg(&w3[i*128 + tid]),     a0);
        a1 = fmaf(s_in[i+1], __ldg(&w3[(i+1)*128 + tid]), a1);
    }
    g_x3[b*1536 + (oy*4 + ox)*128 + tid] = fmaxf(a0 + a1 + b3[tid], 0.f);
}

// dense split-K x2, f32x2, pipelined wd loads. grid(188,2), 256 thr.  [proven ~100us]
__global__ __launch_bounds__(256) void dense_kernel(const float* __restrict__ wd)
{
    __shared__ float2 s_x2[8*768];
    const int tid = threadIdx.x;
    const int kh = blockIdx.y, k0 = kh * 768;
    const int n = blockIdx.x * 256 + tid;
    for (int i = tid; i < 8*768; i += 256) {
        int bp = i / 768, k = i - bp*768;
        s_x2[i] = make_float2(g_x3[(2*bp)*1536 + k0 + k], g_x3[(2*bp+1)*1536 + k0 + k]);
    }
    __syncthreads();
    if (n >= 48000) return;

    ull acc[8];
#pragma unroll
    for (int bp = 0; bp < 8; ++bp) acc[bp] = 0ull;

    const float* wp = wd + (size_t)k0 * 48000 + n;
    float wA[8], wB[8];
#pragma unroll
    for (int j = 0; j < 8; ++j) wA[j] = wp[(size_t)j * 48000];

    for (int kk = 0; kk < 768; kk += 16) {
#pragma unroll
        for (int j = 0; j < 8; ++j) wB[j] = wp[(size_t)(kk + 8 + j) * 48000];
        {
            ull wq[8];
#pragma unroll
            for (int j = 0; j < 8; ++j) wq[j] = pack2(wA[j], wA[j]);
#pragma unroll
            for (int bp = 0; bp < 8; ++bp) {
                const ulonglong2* xp = (const ulonglong2*)&s_x2[bp*768 + kk];
                ulonglong2 xa = xp[0], xb = xp[1], xc = xp[2], xd = xp[3];
                fma2(acc[bp], xa.x, wq[0]); fma2(acc[bp], xa.y, wq[1]);
                fma2(acc[bp], xb.x, wq[2]); fma2(acc[bp], xb.y, wq[3]);
                fma2(acc[bp], xc.x, wq[4]); fma2(acc[bp], xc.y, wq[5]);
                fma2(acc[bp], xd.x, wq[6]); fma2(acc[bp], xd.y, wq[7]);
            }
        }
        const int kn = (kk + 16 < 768) ? (kk + 16) : 0;
#pragma unroll
        for (int j = 0; j < 8; ++j) wA[j] = wp[(size_t)(kn + j) * 48000];
        {
            ull wq[8];
#pragma unroll
            for (int j = 0; j < 8; ++j) wq[j] = pack2(wB[j], wB[j]);
#pragma unroll
            for (int bp = 0; bp < 8; ++bp) {
                const ulonglong2* xp = (const ulonglong2*)&s_x2[bp*768 + kk + 8];
                ulonglong2 xa = xp[0], xb = xp[1], xc = xp[2], xd = xp[3];
                fma2(acc[bp], xa.x, wq[0]); fma2(acc[bp], xa.y, wq[1]);
                fma2(acc[bp], xb.x, wq[2]); fma2(acc[bp], xb.y, wq[3]);
                fma2(acc[bp], xc.x, wq[4]); fma2(acc[bp], xc.y, wq[5]);
                fma2(acc[bp], xd.x, wq[6]); fma2(acc[bp], xd.y, wq[7]);
            }
        }
    }
#pragma unroll
    for (int bp = 0; bp < 8; ++bp) {
        float2 v = unpack2(acc[bp]);
        g_part[(kh*16 + 2*bp)*48000 + n]     = v.x;
        g_part[(kh*16 + 2*bp + 1)*48000 + n] = v.y;
    }
}

// epilogue: out = relu(part0 + part1 + bd); resets persistent-NMS state
__global__ __launch_bounds__(256) void dense_epilogue_kernel(
    const float* __restrict__ bd, float* __restrict__ out)
{
    int i = blockIdx.x * 256 + threadIdx.x;
    if (i < 20) g_round_key[i] = 0ull;
    if (i == 20) { g_bar_count = 0; g_bar_phase = 0; }
    if (i >= 768000) return;
    int n = i % 48000;
    int b = i / 48000;
    float v = g_part[b*48000 + n] + g_part[(16 + b)*48000 + n] + bd[n];
    out[i] = fmaxf(v, 0.f);
}

// decode (faithful flat reshapes) + threshold; writes ALL 76800 slots  [proven]
__global__ __launch_bounds__(256) void transform_kernel(const float* __restrict__ p)
{
    const int j = blockIdx.x * 256 + threadIdx.x;

    float center[2], wh[2];
#pragma unroll
    for (int c = 0; c < 2; ++c) {
        int f = 2*j + c;
        int sa = f / 76800;  int r  = f - sa*76800;
        int sb = r / 4800;   int r2 = r - sb*4800;
        int sgy = r2 / 120;  int r3 = r2 - sgy*120;
        int sgx = r3 >> 1;   int sc = r3 & 1;
        const float* pc = p + ((sb*40 + sgy)*60 + sgx)*20;
        int off = sa ? 10 : 0;
        center[c] = sigmoidf_(pc[off + sc]) + (sc == 0 ? (float)sgx : (float)sgy);
        float anch = (sgx >= 30) ? (sc == 0 ? 0.5f : 1.0f) : (sc == 0 ? 1.0f : 0.5f);
        wh[c] = expf(pc[off + 2 + sc]) * anch;
    }
    int sa = j / 38400;  int r = j - sa*38400;
    int sb = r / 2400;   int rr = r - sb*2400;
    int sgy = rr / 60;   int sgx = rr - sgy*60;
    float obj = sigmoidf_(p[((sb*40 + sgy)*60 + sgx)*20 + (sa ? 14 : 4)]);

    float best = -1.f; int bcls = 0;
#pragma unroll
    for (int c5 = 0; c5 < 5; ++c5) {
        int g = 5*j + c5;
        int ta = g / 192000;  int q  = g - ta*192000;
        int tb = q / 12000;   int q2 = q - tb*12000;
        int tgy = q2 / 300;   int q3 = q2 - tgy*300;
        int tgx = q3 / 5;     int tc = q3 - tgx*5;
        float cl = sigmoidf_(p[((tb*40 + tgy)*60 + tgx)*20 + (ta ? 15 : 5) + tc]);
        float s = obj * cl;
        if (s > best) { best = s; bcls = c5; }
    }

    float y1 = (center[1] - wh[1]*0.5f) * 400.f;
    float x1 = (center[0] - wh[0]*0.5f) * 600.f;
    float y2 = (center[1] + wh[1]*0.5f) * 400.f;
    float x2 = (center[0] + wh[0]*0.5f) * 600.f;
    float area = fmaxf(y2 - y1, 0.f) * fmaxf(x2 - x1, 0.f);
    float score = (best >= 0.3f) ? best : NEGV;
    g_cand_box[j]  = make_float4(y1, x1, y2, x2);
    g_cand_meta[j] = make_float4(score, area, 0.f, (float)bcls);
}

// Persistent NMS: 148 blocks x 512 thr (all resident), candidates in smem,
// 20 rounds, one grid barrier each (per-round key slots -> no reset race)  [proven R11]
#define NMS_BLOCKS 148
#define CPB 519
__global__ __launch_bounds__(512) void nms_persistent_kernel(float* __restrict__ out)
{
    __shared__ float  s_score[CPB];
    __shared__ float4 s_box[CPB];
    __shared__ float  s_area[CPB];
    __shared__ ull    s_key[16];
    __shared__ float4 s_selb;
    __shared__ float  s_sela;
    __shared__ int    s_selpos;

    const int tid = threadIdx.x;
    const int base = blockIdx.x * CPB;
    const int cnt = min(CPB, 76800 - base);

    for (int i = tid; i < cnt; i += 512) {
        float4 mt = g_cand_meta[base + i];
        s_score[i] = mt.x;
        s_area[i]  = mt.y;
        s_box[i]   = g_cand_box[base + i];
    }
    __syncthreads();

    for (int t = 0; t < 20; ++t) {
        ull key = 0ull;
        for (int i = tid; i < cnt; i += 512) {
            float s = s_score[i];
            if (s != NEGV) {
                ull k = ((ull)__float_as_uint(s) << 32) | (ull)(0xffffffffu - (unsigned)(base + i));
                if (k > key) key = k;
            }
        }
#pragma unroll
        for (int off = 16; off > 0; off >>= 1) {
            ull o = __shfl_down_sync(0xffffffffu, key, off);
            if (o > key) key = o;
        }
        if ((tid & 31) == 0) s_key[tid >> 5] = key;
        __syncthreads();
        if (tid == 0) {
            ull bk = s_key[0];
#pragma unroll
            for (int w = 1; w < 16; ++w) if (s_key[w] > bk) bk = s_key[w];
            if (bk) atomicMax(&g_round_key[t], bk);
            __threadfence();
            int ticket = atomicAdd(&g_bar_count, 1);
            if (ticket == NMS_BLOCKS - 1) {
                g_bar_count = 0;
                __threadfence();
                g_bar_phase = t + 1;
            } else {
                while (g_bar_phase < t + 1) __nanosleep(64);
            }
            ull k = g_round_key[t];
            if (k != 0ull) {
                int pos = (int)(0xffffffffu - (unsigned)(k & 0xffffffffu));
                float score = __uint_as_float((unsigned)(k >> 32));
                float4 bx = g_cand_box[pos];
                float4 m2 = g_cand_meta[pos];
                s_selpos = pos; s_selb = bx; s_sela = m2.y;
                if (blockIdx.x == 0) {
                    out[768080 + t] = score;
                    out[768000 + 4*t + 0] = bx.x;
                    out[768000 + 4*t + 1] = bx.y;
                    out[768000 + 4*t + 2] = bx.z;
                    out[768000 + 4*t + 3] = bx.w;
                    out[768100 + t] = m2.w;
                }
            } else {
                s_selpos = -1;
                if (blockIdx.x == 0) {
                    out[768080 + t] = 0.f;
                    out[768000 + 4*t + 0] = 0.f;
                    out[768000 + 4*t + 1] = 0.f;
                    out[768000 + 4*t + 2] = 0.f;
                    out[768000 + 4*t + 3] = 0.f;
                    out[768100 + t] = 0.f;
                }
            }
        }
        __syncthreads();
        const int selPos = s_selpos;
        if (selPos >= 0) {
            const float4 sb = s_selb;
            const float sa = s_sela;
            for (int i = tid; i < cnt; i += 512) {
                float s = s_score[i];
                if (s != NEGV) {
                    float4 bx = s_box[i];
                    float yy1 = fmaxf(sb.x, bx.x), xx1 = fmaxf(sb.y, bx.y);
                    float yy2 = fminf(sb.z, bx.z), xx2 = fminf(sb.w, bx.w);
                    float inter = fmaxf(yy2 - yy1, 0.f) * fmaxf(xx2 - xx1, 0.f);
                    float iou = inter / (sa + s_area[i] - inter + 1e-9f);
                    if (iou > 0.4f || (base + i) == selPos) s_score[i] = NEGV;
                }
            }
        }
        __syncthreads();
    }
}

extern "C" void kernel_launch(void* const* d_in, const int* in_sizes, int n_in,
                              void* d_out, int out_size) {
    const float* img = (const float*)d_in[0];
    const float* w1  = (const float*)d_in[1];
    const float* b1  = (const float*)d_in[2];
    const float* w2  = (const float*)d_in[3];
    const float* b2  = (const float*)d_in[4];
    const float* w3  = (const float*)d_in[5];
    const float* b3  = (const float*)d_in[6];
    const float* wd  = (const float*)d_in[7];
    const float* bd  = (const float*)d_in[8];
    float* out = (float*)d_out;

    conv1_pool_kernel<<<dim3(10, 98, 16), 256>>>(img, w1, b1);
    conv2_pool_kernel<<<dim3(9, 6, 16), 256>>>(w2, b2);
    conv3_kernel<<<dim3(4, 3, 16), 128>>>(w3, b3);
    dense_kernel<<<dim3(188, 2), 256>>>(wd);
    dense_epilogue_kernel<<<3000, 256>>>(bd, out);
    transform_kernel<<<300, 256>>>(out);
    nms_persistent_kernel<<<NMS_BLOCKS, 512>>>(out);
}